// round 14
// baseline (speedup 1.0000x reference)
#include <cuda_runtime.h>
#include <cuda_bf16.h>
#include <cuda_fp16.h>
#include <math.h>
#include <cstdint>

// Problem constants
#define BATCH 2
#define SEQ   4096
#define EMB   1024
#define HEADS 16
#define HDIM  64
#define MROWS (BATCH*SEQ)   // 8192

// ---------------- scratch (static device globals; no runtime allocation) ----
__device__ __half g_Qh[(size_t)BATCH*HEADS*SEQ*HDIM];  // (B,H,T,D), scaled 0.125*log2e
__device__ __half g_Kh[(size_t)BATCH*HEADS*SEQ*HDIM];
__device__ __half g_Vh[(size_t)BATCH*HEADS*SEQ*HDIM];
__device__ __half g_AOh[(size_t)BATCH*SEQ*EMB];        // (B,T,E)
__device__ __half g_xh[(size_t)MROWS*EMB];
__device__ __half g_Wh[4][(size_t)EMB*EMB];            // Wq,Wk,Wv,Wo as half

__device__ __forceinline__ uint32_t pack_h2(float a, float b) {
    __half2 h = __floats2half2_rn(a, b);
    return *(uint32_t*)&h;
}

__device__ __forceinline__ uint32_t h2exp2(uint32_t x) {
    uint32_t r;
    asm("ex2.approx.f16x2 %0, %1;" : "=r"(r) : "r"(x));
    return r;
}

__device__ __forceinline__ float ex2f(float x) {
    float r;
    asm("ex2.approx.f32 %0, %1;" : "=f"(r) : "f"(x));
    return r;
}

__device__ __forceinline__ uint32_t cvta_smem(const void* p) {
    uint32_t a;
    asm("{ .reg .u64 t; cvta.to.shared.u64 t, %1; cvt.u32.u64 %0, t; }"
        : "=r"(a) : "l"(p));
    return a;
}

__device__ __forceinline__ void cp16(uint32_t smem, const void* g) {
    asm volatile("cp.async.cg.shared.global [%0], [%1], 16;" :: "r"(smem), "l"(g));
}
#define CP_COMMIT() asm volatile("cp.async.commit_group;" ::: "memory")
#define CP_WAIT(n)  asm volatile("cp.async.wait_group %0;" :: "n"(n) : "memory")

__device__ __forceinline__ void ldm_x4(
    uint32_t& r0, uint32_t& r1, uint32_t& r2, uint32_t& r3, uint32_t addr)
{
    asm volatile("ldmatrix.sync.aligned.m8n8.x4.shared.b16 {%0,%1,%2,%3}, [%4];"
        : "=r"(r0), "=r"(r1), "=r"(r2), "=r"(r3) : "r"(addr));
}

__device__ __forceinline__ void ldm_x4_t(
    uint32_t& r0, uint32_t& r1, uint32_t& r2, uint32_t& r3, uint32_t addr)
{
    asm volatile("ldmatrix.sync.aligned.m8n8.x4.trans.shared.b16 {%0,%1,%2,%3}, [%4];"
        : "=r"(r0), "=r"(r1), "=r"(r2), "=r"(r3) : "r"(addr));
}

__device__ __forceinline__ void mma_fp16(
    float& c0, float& c1, float& c2, float& c3,
    uint32_t a0, uint32_t a1, uint32_t a2, uint32_t a3,
    uint32_t b0, uint32_t b1)
{
    asm volatile(
        "mma.sync.aligned.m16n8k16.row.col.f32.f16.f16.f32 "
        "{%0,%1,%2,%3}, {%4,%5,%6,%7}, {%8,%9}, {%0,%1,%2,%3};"
        : "+f"(c0), "+f"(c1), "+f"(c2), "+f"(c3)
        : "r"(a0), "r"(a1), "r"(a2), "r"(a3), "r"(b0), "r"(b1));
}

// ---------------- fused fp32 -> fp16 convert (x + 4 weights, 16/thread) -----
#define NX   (MROWS*EMB)     // 8388608
#define NWEL (EMB*EMB)       // 1048576 = 2^20

__global__ __launch_bounds__(256) void cvt_all(
    const float* __restrict__ x,
    const float* __restrict__ wq, const float* __restrict__ wk,
    const float* __restrict__ wv, const float* __restrict__ wo,
    __half* __restrict__ xh, __half* __restrict__ wh)
{
    size_t i = ((size_t)blockIdx.x * 256 + threadIdx.x) * 16;
    const float* src;
    __half* dst;
    size_t off;
    if (i < NX) { src = x; dst = xh; off = i; }
    else {
        size_t j = i - NX;
        int w = (int)(j >> 20);
        src = (w == 0) ? wq : (w == 1) ? wk : (w == 2) ? wv : wo;
        dst = wh + (size_t)w * NWEL;
        off = j & (NWEL - 1);
    }
    #pragma unroll
    for (int l = 0; l < 2; l++) {
        float4 a = *(const float4*)&src[off + l * 8];
        float4 b = *(const float4*)&src[off + l * 8 + 4];
        *(uint4*)&dst[off + l * 8] = make_uint4(
            pack_h2(a.x, a.y), pack_h2(a.z, a.w),
            pack_h2(b.x, b.y), pack_h2(b.z, b.w));
    }
}

// ============================================================================
// fp16 GEMM core: K-chunk 32, 4-stage cp.async ring (prefetch distance 3).
// CTA 128x128x32, 256 thr, warp tile 64x32, ldmatrix fragments.
// Wait arithmetic: at iter kc, committed groups 0..kc+2; WAIT(2) => group kc done.
// ============================================================================
#define GPH    40                      // halves per smem row (80 B)
#define GSTGB  (128 * GPH * 2)         // bytes per operand per stage (10240)
#define GSB    (2 * GSTGB)             // bytes per stage (A+B) = 20480
#define GSMEM  (4 * GSB)               // 81920
#define NCHUNK (EMB / 32)              // 32

struct GemmCore {
    float c[4][4][4];
    int qrow, qcol, wm0, wn0;

    __device__ __forceinline__ void run(
        const __half* __restrict__ A, const __half* __restrict__ W,
        int row0, int col0)
    {
        extern __shared__ __align__(16) char gsm[];
        const uint32_t asb = cvta_smem(gsm);
        const uint32_t bsb = asb + GSTGB;

        const int tid = threadIdx.x;
        const int wid = tid >> 5;
        const int lid = tid & 31;
        qrow = lid >> 2;
        qcol = lid & 3;
        wm0 = (wid & 1) * 64;
        wn0 = (wid >> 1) * 32;

        const int i16 = lid & 15;
        const int g8  = ((lid >> 4) & 1) * 8;
        uint32_t aaddr[4], baddr[2];
        #pragma unroll
        for (int mi = 0; mi < 4; mi++)
            aaddr[mi] = asb + (uint32_t)(((wm0 + mi * 16 + i16) * GPH + g8) * 2);
        #pragma unroll
        for (int nip = 0; nip < 2; nip++)
            baddr[nip] = bsb + (uint32_t)(((wn0 + nip * 16 + i16) * GPH + g8) * 2);

        auto prefetch = [&](int kc, int slot) {
            const int k0 = kc * 32;
            const uint32_t so = slot * GSB;
            #pragma unroll
            for (int l = 0; l < 2; l++) {
                int idx = tid + l * 256;       // 0..511
                int r   = idx >> 2;            // 0..127
                int c8  = (idx & 3) * 8;       // 0,8,16,24
                uint32_t off = (uint32_t)(r * GPH + c8) * 2 + so;
                cp16(asb + off, &A[(size_t)(row0 + r) * EMB + k0 + c8]);
                cp16(bsb + off, &W[(size_t)(col0 + r) * EMB + k0 + c8]);
            }
        };

        #pragma unroll
        for (int i = 0; i < 4; i++)
            #pragma unroll
            for (int j = 0; j < 4; j++)
                #pragma unroll
                for (int f = 0; f < 4; f++) c[i][j][f] = 0.f;

        prefetch(0, 0); CP_COMMIT();
        prefetch(1, 1); CP_COMMIT();
        prefetch(2, 2); CP_COMMIT();

        for (int kc = 0; kc < NCHUNK; kc++) {
            const int left = NCHUNK - 1 - kc;      // chunks committed beyond kc
            if (left >= 2)      { CP_WAIT(2); }
            else if (left == 1) { CP_WAIT(1); }
            else                { CP_WAIT(0); }
            __syncthreads();                       // chunk kc ready, old slot drained
            if (kc + 3 < NCHUNK) {
                prefetch(kc + 3, (kc + 3) & 3);
                CP_COMMIT();
            }
            const uint32_t so = (kc & 3) * GSB;

            #pragma unroll
            for (int ks = 0; ks < 2; ks++) {
                const uint32_t koff = so + ks * 32;
                uint32_t a[4][4], b[4][2];
                #pragma unroll
                for (int mi = 0; mi < 4; mi++)
                    ldm_x4(a[mi][0], a[mi][1], a[mi][2], a[mi][3], aaddr[mi] + koff);
                #pragma unroll
                for (int nip = 0; nip < 2; nip++) {
                    uint32_t r0, r1, r2, r3;
                    ldm_x4(r0, r1, r2, r3, baddr[nip] + koff);
                    b[2*nip][0] = r0;   b[2*nip][1] = r2;
                    b[2*nip+1][0] = r1; b[2*nip+1][1] = r3;
                }
                #pragma unroll
                for (int mi = 0; mi < 4; mi++)
                    #pragma unroll
                    for (int ni = 0; ni < 4; ni++)
                        mma_fp16(c[mi][ni][0], c[mi][ni][1], c[mi][ni][2], c[mi][ni][3],
                                 a[mi][0], a[mi][1], a[mi][2], a[mi][3],
                                 b[ni][0], b[ni][1]);
            }
        }
    }
};

// QKV fused: blockIdx.z selects weight / output / scale; scatter half (B,H,T,D)
__global__ __launch_bounds__(256) void gemm_qkv(
    const __half* __restrict__ A, const __half* __restrict__ Wbase,
    __half* __restrict__ Qo, __half* __restrict__ Ko, __half* __restrict__ Vo,
    float qscale)
{
    const int z = blockIdx.z;
    const __half* W = Wbase + (size_t)z * NWEL;
    __half* out = (z == 0) ? Qo : (z == 1) ? Ko : Vo;
    const float scale = (z == 0) ? qscale : 1.0f;

    GemmCore gc;
    gc.run(A, W, blockIdx.y * 128, blockIdx.x * 128);

    #pragma unroll
    for (int mi = 0; mi < 4; mi++) {
        #pragma unroll
        for (int hf = 0; hf < 2; hf++) {
            const int m = blockIdx.y * 128 + gc.wm0 + mi * 16 + gc.qrow + hf * 8;
            const int bi = m >> 12;
            const int t  = m & (SEQ - 1);
            #pragma unroll
            for (int ni = 0; ni < 4; ni++) {
                const int n = blockIdx.x * 128 + gc.wn0 + ni * 8 + gc.qcol * 2;
                const int h = n >> 6;
                const int d = n & (HDIM - 1);
                *(uint32_t*)&out[(((size_t)bi * HEADS + h) * SEQ + t) * HDIM + d] =
                    pack_h2(gc.c[mi][ni][hf * 2] * scale, gc.c[mi][ni][hf * 2 + 1] * scale);
            }
        }
    }
}

// Final projection: A half, fp32 row-major out + bias
__global__ __launch_bounds__(256) void gemm_out(
    const __half* __restrict__ A, const __half* __restrict__ W,
    const float* __restrict__ bias, float* __restrict__ out)
{
    GemmCore gc;
    gc.run(A, W, blockIdx.y * 128, blockIdx.x * 128);

    #pragma unroll
    for (int mi = 0; mi < 4; mi++) {
        #pragma unroll
        for (int hf = 0; hf < 2; hf++) {
            const int m = blockIdx.y * 128 + gc.wm0 + mi * 16 + gc.qrow + hf * 8;
            #pragma unroll
            for (int ni = 0; ni < 4; ni++) {
                const int n = blockIdx.x * 128 + gc.wn0 + ni * 8 + gc.qcol * 2;
                float2 bb = *(const float2*)&bias[n];
                *(float2*)&out[(size_t)m * EMB + n] =
                    make_float2(gc.c[mi][ni][hf * 2] + bb.x,
                                gc.c[mi][ni][hf * 2 + 1] + bb.y);
            }
        }
    }
}

// ============================================================================
// Flash attention: fp16, ldmatrix + 3-stage cp.async K/V ring (distance 2).
// Wait arithmetic: at iter jt, committed groups 0..jt+1; WAIT(1) => group jt
// complete, group jt+1 (distance-2 prefetch) stays in flight. WAIT(0) at end.
// exp2-domain softmax, 8 warps / 128 q-rows per CTA, LPT ordering.
// ============================================================================
#define FP    72
#define FTILE (64 * FP)            // halves per tile
#define FBUFB (2 * FTILE * 2)      // bytes per (Ks,Vs) stage = 18432
#define FSMEM (3 * FBUFB + 2 * FTILE * 2)   // 3 stages + Ps = 73728

__global__ __launch_bounds__(256, 2) void flash_mma(
    const __half* __restrict__ Q, const __half* __restrict__ K,
    const __half* __restrict__ V, __half* __restrict__ O)
{
    extern __shared__ __align__(16) char dynsm[];
    __half* Ks0 = (__half*)dynsm;                  // stage s at + s*FBUFB
    __half* Vs0 = Ks0 + FTILE;
    __half* Ps  = (__half*)(dynsm + 3 * FBUFB);    // Ps[grp] at + grp*FTILE

    const int qt = gridDim.x - 1 - blockIdx.x;     // heavy tiles first (LPT)
    const int bh = blockIdx.y;
    const size_t base = (size_t)bh * SEQ * HDIM;
    const __half* Qb = Q + base;
    const __half* Kb = K + base;
    const __half* Vb = V + base;

    const int tid  = threadIdx.x;
    const int wid  = tid >> 5;
    const int grp  = wid >> 2;
    const int w16  = (wid & 3) * 16;
    const int lid  = tid & 31;
    const int qrow = lid >> 2;
    const int qcol = lid & 3;
    const int q0   = qt * 128;
    const int jtmax = 2 * qt + grp;
    const int last  = 2 * qt + 1;
    const unsigned FULL = 0xffffffffu;

    const int i8 = lid & 7;
    const int g1 = (lid >> 3) & 1;
    const int g2 = (lid >> 4) & 1;
    __half* Pg = Ps + grp * FTILE;
    const uint32_t paddr = cvta_smem(Pg) +
        (uint32_t)(((w16 + g1 * 8 + i8) * FP + g2 * 8) * 2);
    uint32_t kaddr[4], vaddr[4];
    {
        const uint32_t kb_ = cvta_smem(Ks0);
        const uint32_t vb_ = cvta_smem(Vs0);
        #pragma unroll
        for (int ntp = 0; ntp < 4; ntp++) {
            kaddr[ntp] = kb_ + (uint32_t)((((2 * ntp + g2) * 8 + i8) * FP + g1 * 8) * 2);
            vaddr[ntp] = vb_ + (uint32_t)(((g1 * 8 + i8) * FP + (2 * ntp + g2) * 8) * 2);
        }
    }

    const uint32_t ksb = cvta_smem(Ks0);
    const uint32_t vsb = cvta_smem(Vs0);
    auto prefetch = [&](int jt, int s) {
        #pragma unroll
        for (int l = 0; l < 2; l++) {
            int idx = tid + l * 256;
            int r   = idx >> 3;
            int c8  = (idx & 7) * 8;
            size_t g = (size_t)(jt * 64 + r) * HDIM + c8;
            uint32_t off = (uint32_t)(r * FP + c8) * 2 + s * FBUFB;
            cp16(ksb + off, &Kb[g]);
            cp16(vsb + off, &Vb[g]);
        }
    };

    prefetch(0, 0); CP_COMMIT();
    prefetch(1, 1); CP_COMMIT();       // last >= 1 always

    #pragma unroll
    for (int l = 0; l < 4; l++) {
        int idx = tid + l * 256;
        int r   = idx >> 3;
        int c8  = (idx & 7) * 8;
        *(uint4*)&Ps[(r >> 6) * FTILE + (r & 63) * FP + c8] =
            *(const uint4*)&Qb[(size_t)(q0 + r) * HDIM + c8];
    }
    __syncthreads();

    uint32_t aq[4][4];
    #pragma unroll
    for (int ks = 0; ks < 4; ks++)
        ldm_x4(aq[ks][0], aq[ks][1], aq[ks][2], aq[ks][3], paddr + ks * 32);

    float o[8][4];
    #pragma unroll
    for (int nt = 0; nt < 8; nt++)
        #pragma unroll
        for (int f = 0; f < 4; f++) o[nt][f] = 0.f;
    float m_lo = -INFINITY, m_hi = -INFINITY, l_lo = 0.f, l_hi = 0.f;

    for (int jt = 0; jt <= last; jt++) {
        // committed groups: 0..min(jt+1,last). Guarantee group jt complete:
        if (jt < last) { CP_WAIT(1); } else { CP_WAIT(0); }
        __syncthreads();
        if (jt + 2 <= last) {
            prefetch(jt + 2, (jt + 2) % 3);
            CP_COMMIT();
        }

        if (jt <= jtmax) {
            const uint32_t boff = (jt % 3) * FBUFB;

            float c[8][4];
            #pragma unroll
            for (int nt = 0; nt < 8; nt++)
                #pragma unroll
                for (int f = 0; f < 4; f++) c[nt][f] = 0.f;

            #pragma unroll
            for (int ks = 0; ks < 4; ks++) {
                #pragma unroll
                for (int ntp = 0; ntp < 4; ntp++) {
                    uint32_t b0, b1, b2, b3;
                    ldm_x4(b0, b1, b2, b3, kaddr[ntp] + boff + ks * 32);
                    mma_fp16(c[2*ntp][0], c[2*ntp][1], c[2*ntp][2], c[2*ntp][3],
                             aq[ks][0], aq[ks][1], aq[ks][2], aq[ks][3], b0, b1);
                    mma_fp16(c[2*ntp+1][0], c[2*ntp+1][1], c[2*ntp+1][2], c[2*ntp+1][3],
                             aq[ks][0], aq[ks][1], aq[ks][2], aq[ks][3], b2, b3);
                }
            }

            if (jt == jtmax) {
                #pragma unroll
                for (int nt = 0; nt < 8; nt++) {
                    #pragma unroll
                    for (int f = 0; f < 4; f++) {
                        int kloc = nt * 8 + 2 * qcol + (f & 1);
                        int qloc = w16 + qrow + ((f >> 1) * 8);
                        if (kloc > qloc) c[nt][f] = -INFINITY;
                    }
                }
            }

            float tl = -INFINITY, th = -INFINITY;
            #pragma unroll
            for (int nt = 0; nt < 8; nt++) {
                tl = fmaxf(tl, fmaxf(c[nt][0], c[nt][1]));
                th = fmaxf(th, fmaxf(c[nt][2], c[nt][3]));
            }
            tl = fmaxf(tl, __shfl_xor_sync(FULL, tl, 1, 4));
            tl = fmaxf(tl, __shfl_xor_sync(FULL, tl, 2, 4));
            th = fmaxf(th, __shfl_xor_sync(FULL, th, 1, 4));
            th = fmaxf(th, __shfl_xor_sync(FULL, th, 2, 4));

            float mn_lo = fmaxf(m_lo, tl);
            float mn_hi = fmaxf(m_hi, th);
            float f_lo = ex2f(m_lo - mn_lo);
            float f_hi = ex2f(m_hi - mn_hi);

            float rs_lo = 0.f, rs_hi = 0.f;
            #pragma unroll
            for (int nt = 0; nt < 8; nt++) {
                uint32_t e01 = h2exp2(pack_h2(c[nt][0] - mn_lo, c[nt][1] - mn_lo));
                uint32_t e23 = h2exp2(pack_h2(c[nt][2] - mn_hi, c[nt][3] - mn_hi));
                int col = nt * 8 + 2 * qcol;
                *(uint32_t*)&Pg[(w16 + qrow) * FP + col]     = e01;
                *(uint32_t*)&Pg[(w16 + qrow + 8) * FP + col] = e23;
                float2 f01 = __half22float2(*(__half2*)&e01);
                float2 f23 = __half22float2(*(__half2*)&e23);
                rs_lo += f01.x + f01.y;
                rs_hi += f23.x + f23.y;
            }
            rs_lo += __shfl_xor_sync(FULL, rs_lo, 1, 4);
            rs_lo += __shfl_xor_sync(FULL, rs_lo, 2, 4);
            rs_hi += __shfl_xor_sync(FULL, rs_hi, 1, 4);
            rs_hi += __shfl_xor_sync(FULL, rs_hi, 2, 4);

            l_lo = l_lo * f_lo + rs_lo;
            l_hi = l_hi * f_hi + rs_hi;
            m_lo = mn_lo;
            m_hi = mn_hi;
            #pragma unroll
            for (int nt = 0; nt < 8; nt++) {
                o[nt][0] *= f_lo; o[nt][1] *= f_lo;
                o[nt][2] *= f_hi; o[nt][3] *= f_hi;
            }
            __syncwarp();

            #pragma unroll
            for (int ks = 0; ks < 4; ks++) {
                uint32_t a0, a1, a2, a3;
                ldm_x4(a0, a1, a2, a3, paddr + ks * 32);
                #pragma unroll
                for (int ntp = 0; ntp < 4; ntp++) {
                    uint32_t v0, v1, v2, v3;
                    ldm_x4_t(v0, v1, v2, v3, vaddr[ntp] + boff + ks * (16 * FP * 2));
                    mma_fp16(o[2*ntp][0], o[2*ntp][1], o[2*ntp][2], o[2*ntp][3],
                             a0, a1, a2, a3, v0, v1);
                    mma_fp16(o[2*ntp+1][0], o[2*ntp+1][1], o[2*ntp+1][2], o[2*ntp+1][3],
                             a0, a1, a2, a3, v2, v3);
                }
            }
        }
        __syncthreads();
    }

    const float inv_lo = 1.f / l_lo;
    const float inv_hi = 1.f / l_hi;
    const int b = bh >> 4;
    const int h = bh & (HEADS - 1);
    const int row_lo = q0 + grp * 64 + w16 + qrow;
    const int row_hi = row_lo + 8;
    #pragma unroll
    for (int nt = 0; nt < 8; nt++) {
        const int e = h * HDIM + nt * 8 + 2 * qcol;
        *(uint32_t*)&O[((size_t)(b * SEQ) + row_lo) * EMB + e] =
            pack_h2(o[nt][0] * inv_lo, o[nt][1] * inv_lo);
        *(uint32_t*)&O[((size_t)(b * SEQ) + row_hi) * EMB + e] =
            pack_h2(o[nt][2] * inv_hi, o[nt][3] * inv_hi);
    }
}

// ---------------- launch -----------------------------------------------------
extern "C" void kernel_launch(void* const* d_in, const int* in_sizes, int n_in,
                              void* d_out, int out_size)
{
    const float* x  = (const float*)d_in[0];
    const float* Wq = (const float*)d_in[1];
    const float* Wk = (const float*)d_in[2];
    const float* Wv = (const float*)d_in[3];
    const float* Wo = (const float*)d_in[4];
    const float* bo = (const float*)d_in[5];
    float* out = (float*)d_out;

    __half *Qp, *Kp, *Vp, *Ap, *xh, *Wh;
    cudaGetSymbolAddress((void**)&Qp, g_Qh);
    cudaGetSymbolAddress((void**)&Kp, g_Kh);
    cudaGetSymbolAddress((void**)&Vp, g_Vh);
    cudaGetSymbolAddress((void**)&Ap, g_AOh);
    cudaGetSymbolAddress((void**)&xh, g_xh);
    cudaGetSymbolAddress((void**)&Wh, g_Wh);

    cvt_all<<<(NX + 4 * NWEL) / (256 * 16), 256>>>(x, Wq, Wk, Wv, Wo, xh, Wh);

    cudaFuncSetAttribute(gemm_qkv, cudaFuncAttributeMaxDynamicSharedMemorySize, GSMEM);
    cudaFuncSetAttribute(gemm_out, cudaFuncAttributeMaxDynamicSharedMemorySize, GSMEM);

    const float qscale = 0.125f * 1.4426950408889634f;   // fold log2e
    dim3 gqkv(EMB / 128, MROWS / 128, 3);                // (8, 64, 3)
    gemm_qkv<<<gqkv, 256, GSMEM>>>(xh, Wh, Qp, Kp, Vp, qscale);

    cudaFuncSetAttribute(flash_mma, cudaFuncAttributeMaxDynamicSharedMemorySize, FSMEM);
    flash_mma<<<dim3(SEQ / 128, BATCH * HEADS), 256, FSMEM>>>(Qp, Kp, Vp, Ap);

    dim3 gg(EMB / 128, MROWS / 128);   // (8, 64)
    gemm_out<<<gg, 256, GSMEM>>>(Ap, Wh + 3 * (size_t)NWEL, bo, out);
}

// round 15
// speedup vs baseline: 1.0888x; 1.0888x over previous
#include <cuda_runtime.h>
#include <cuda_bf16.h>
#include <cuda_fp16.h>
#include <math.h>
#include <cstdint>

// Problem constants
#define BATCH 2
#define SEQ   4096
#define EMB   1024
#define HEADS 16
#define HDIM  64
#define MROWS (BATCH*SEQ)   // 8192

// ---------------- scratch (static device globals; no runtime allocation) ----
__device__ __half g_Qh[(size_t)BATCH*HEADS*SEQ*HDIM];  // (B,H,T,D), scaled 0.125*log2e
__device__ __half g_Kh[(size_t)BATCH*HEADS*SEQ*HDIM];
__device__ __half g_Vh[(size_t)BATCH*HEADS*SEQ*HDIM];
__device__ __half g_AOh[(size_t)BATCH*SEQ*EMB];        // (B,T,E)
__device__ __half g_xh[(size_t)MROWS*EMB];
__device__ __half g_Wh[4][(size_t)EMB*EMB];            // Wq,Wk,Wv,Wo as half

__device__ __forceinline__ uint32_t pack_h2(float a, float b) {
    __half2 h = __floats2half2_rn(a, b);
    return *(uint32_t*)&h;
}

__device__ __forceinline__ uint32_t h2exp2(uint32_t x) {
    uint32_t r;
    asm("ex2.approx.f16x2 %0, %1;" : "=r"(r) : "r"(x));
    return r;
}

__device__ __forceinline__ float ex2f(float x) {
    float r;
    asm("ex2.approx.f32 %0, %1;" : "=f"(r) : "f"(x));
    return r;
}

__device__ __forceinline__ uint32_t cvta_smem(const void* p) {
    uint32_t a;
    asm("{ .reg .u64 t; cvta.to.shared.u64 t, %1; cvt.u32.u64 %0, t; }"
        : "=r"(a) : "l"(p));
    return a;
}

__device__ __forceinline__ void cp16(uint32_t smem, const void* g) {
    asm volatile("cp.async.cg.shared.global [%0], [%1], 16;" :: "r"(smem), "l"(g));
}
#define CP_COMMIT() asm volatile("cp.async.commit_group;" ::: "memory")
#define CP_WAIT(n)  asm volatile("cp.async.wait_group %0;" :: "n"(n) : "memory")

__device__ __forceinline__ void ldm_x4(
    uint32_t& r0, uint32_t& r1, uint32_t& r2, uint32_t& r3, uint32_t addr)
{
    asm volatile("ldmatrix.sync.aligned.m8n8.x4.shared.b16 {%0,%1,%2,%3}, [%4];"
        : "=r"(r0), "=r"(r1), "=r"(r2), "=r"(r3) : "r"(addr));
}

__device__ __forceinline__ void ldm_x4_t(
    uint32_t& r0, uint32_t& r1, uint32_t& r2, uint32_t& r3, uint32_t addr)
{
    asm volatile("ldmatrix.sync.aligned.m8n8.x4.trans.shared.b16 {%0,%1,%2,%3}, [%4];"
        : "=r"(r0), "=r"(r1), "=r"(r2), "=r"(r3) : "r"(addr));
}

__device__ __forceinline__ void mma_fp16(
    float& c0, float& c1, float& c2, float& c3,
    uint32_t a0, uint32_t a1, uint32_t a2, uint32_t a3,
    uint32_t b0, uint32_t b1)
{
    asm volatile(
        "mma.sync.aligned.m16n8k16.row.col.f32.f16.f16.f32 "
        "{%0,%1,%2,%3}, {%4,%5,%6,%7}, {%8,%9}, {%0,%1,%2,%3};"
        : "+f"(c0), "+f"(c1), "+f"(c2), "+f"(c3)
        : "r"(a0), "r"(a1), "r"(a2), "r"(a3), "r"(b0), "r"(b1));
}

// ---------------- fused fp32 -> fp16 convert (x + 4 weights, 16/thread) -----
#define NX   (MROWS*EMB)     // 8388608
#define NWEL (EMB*EMB)       // 1048576 = 2^20

__global__ __launch_bounds__(256) void cvt_all(
    const float* __restrict__ x,
    const float* __restrict__ wq, const float* __restrict__ wk,
    const float* __restrict__ wv, const float* __restrict__ wo,
    __half* __restrict__ xh, __half* __restrict__ wh)
{
    size_t i = ((size_t)blockIdx.x * 256 + threadIdx.x) * 16;
    const float* src;
    __half* dst;
    size_t off;
    if (i < NX) { src = x; dst = xh; off = i; }
    else {
        size_t j = i - NX;
        int w = (int)(j >> 20);
        src = (w == 0) ? wq : (w == 1) ? wk : (w == 2) ? wv : wo;
        dst = wh + (size_t)w * NWEL;
        off = j & (NWEL - 1);
    }
    #pragma unroll
    for (int l = 0; l < 2; l++) {
        float4 a = *(const float4*)&src[off + l * 8];
        float4 b = *(const float4*)&src[off + l * 8 + 4];
        *(uint4*)&dst[off + l * 8] = make_uint4(
            pack_h2(a.x, a.y), pack_h2(a.z, a.w),
            pack_h2(b.x, b.y), pack_h2(b.z, b.w));
    }
}

// ============================================================================
// fp16 GEMM core: CTA 128x64x32, 256 thr, warp tile 32x32 (8 warps, 4m x 2n).
// 3-stage cp.async ring, prefetch distance 2, ldmatrix fragments.
// 32 accumulator regs/thread -> 3-4 CTAs/SM (occupancy fix).
// Wait arithmetic: at iter kc, committed 0..kc+1; WAIT(1) => group kc done.
// ============================================================================
#define GPH    40                      // halves per smem row (80 B)
#define GSTA   (128 * GPH * 2)         // A bytes per stage (10240)
#define GSTB   (64 * GPH * 2)          // B bytes per stage (5120)
#define GSB    (GSTA + GSTB)           // stage bytes = 15360
#define GSMEM  (3 * GSB)               // 46080
#define NCHUNK (EMB / 32)              // 32

struct GemmCore {
    float c[2][4][4];
    int qrow, qcol, wm0, wn0;

    __device__ __forceinline__ void run(
        const __half* __restrict__ A, const __half* __restrict__ W,
        int row0, int col0)
    {
        extern __shared__ __align__(16) char gsm[];
        const uint32_t asb = cvta_smem(gsm);       // A of stage 0
        const uint32_t bsb = asb + GSTA;           // B of stage 0

        const int tid = threadIdx.x;
        const int wid = tid >> 5;
        const int lid = tid & 31;
        qrow = lid >> 2;
        qcol = lid & 3;
        wm0 = (wid & 3) * 32;          // 4 m-positions
        wn0 = (wid >> 2) * 32;         // 2 n-positions

        const int i16 = lid & 15;
        const int g8  = ((lid >> 4) & 1) * 8;
        uint32_t aaddr[2], baddr[2];
        #pragma unroll
        for (int mi = 0; mi < 2; mi++)
            aaddr[mi] = asb + (uint32_t)(((wm0 + mi * 16 + i16) * GPH + g8) * 2);
        #pragma unroll
        for (int nip = 0; nip < 2; nip++)
            baddr[nip] = bsb + (uint32_t)(((wn0 + nip * 16 + i16) * GPH + g8) * 2);

        auto prefetch = [&](int kc, int slot) {
            const int k0 = kc * 32;
            const uint32_t so = slot * GSB;
            #pragma unroll
            for (int l = 0; l < 2; l++) {          // A: 512 cp16
                int idx = tid + l * 256;
                int r   = idx >> 2;                // 0..127
                int c8  = (idx & 3) * 8;
                cp16(asb + so + (uint32_t)(r * GPH + c8) * 2,
                     &A[(size_t)(row0 + r) * EMB + k0 + c8]);
            }
            {                                      // B: 256 cp16
                int r  = tid >> 2;                 // 0..63
                int c8 = (tid & 3) * 8;
                cp16(bsb + so + (uint32_t)(r * GPH + c8) * 2,
                     &W[(size_t)(col0 + r) * EMB + k0 + c8]);
            }
        };

        #pragma unroll
        for (int i = 0; i < 2; i++)
            #pragma unroll
            for (int j = 0; j < 4; j++)
                #pragma unroll
                for (int f = 0; f < 4; f++) c[i][j][f] = 0.f;

        prefetch(0, 0); CP_COMMIT();
        prefetch(1, 1); CP_COMMIT();

        for (int kc = 0; kc < NCHUNK; kc++) {
            if (kc + 1 < NCHUNK) { CP_WAIT(1); } else { CP_WAIT(0); }
            __syncthreads();                       // chunk kc ready, old slot drained
            if (kc + 2 < NCHUNK) {
                prefetch(kc + 2, (kc + 2) % 3);
                CP_COMMIT();
            }
            const uint32_t so = (kc % 3) * GSB;

            #pragma unroll
            for (int ks = 0; ks < 2; ks++) {
                const uint32_t koff = so + ks * 32;
                uint32_t a[2][4], b[4][2];
                #pragma unroll
                for (int mi = 0; mi < 2; mi++)
                    ldm_x4(a[mi][0], a[mi][1], a[mi][2], a[mi][3], aaddr[mi] + koff);
                #pragma unroll
                for (int nip = 0; nip < 2; nip++) {
                    uint32_t r0, r1, r2, r3;
                    ldm_x4(r0, r1, r2, r3, baddr[nip] + koff);
                    b[2*nip][0] = r0;   b[2*nip][1] = r2;
                    b[2*nip+1][0] = r1; b[2*nip+1][1] = r3;
                }
                #pragma unroll
                for (int mi = 0; mi < 2; mi++)
                    #pragma unroll
                    for (int ni = 0; ni < 4; ni++)
                        mma_fp16(c[mi][ni][0], c[mi][ni][1], c[mi][ni][2], c[mi][ni][3],
                                 a[mi][0], a[mi][1], a[mi][2], a[mi][3],
                                 b[ni][0], b[ni][1]);
            }
            __syncthreads();
        }
    }
};

// QKV fused: blockIdx.z selects weight / output / scale; scatter half (B,H,T,D)
__global__ __launch_bounds__(256) void gemm_qkv(
    const __half* __restrict__ A, const __half* __restrict__ Wbase,
    __half* __restrict__ Qo, __half* __restrict__ Ko, __half* __restrict__ Vo,
    float qscale)
{
    const int z = blockIdx.z;
    const __half* W = Wbase + (size_t)z * NWEL;
    __half* out = (z == 0) ? Qo : (z == 1) ? Ko : Vo;
    const float scale = (z == 0) ? qscale : 1.0f;

    GemmCore gc;
    gc.run(A, W, blockIdx.y * 128, blockIdx.x * 64);

    #pragma unroll
    for (int mi = 0; mi < 2; mi++) {
        #pragma unroll
        for (int hf = 0; hf < 2; hf++) {
            const int m = blockIdx.y * 128 + gc.wm0 + mi * 16 + gc.qrow + hf * 8;
            const int bi = m >> 12;
            const int t  = m & (SEQ - 1);
            #pragma unroll
            for (int ni = 0; ni < 4; ni++) {
                const int n = blockIdx.x * 64 + gc.wn0 + ni * 8 + gc.qcol * 2;
                const int h = n >> 6;
                const int d = n & (HDIM - 1);
                *(uint32_t*)&out[(((size_t)bi * HEADS + h) * SEQ + t) * HDIM + d] =
                    pack_h2(gc.c[mi][ni][hf * 2] * scale, gc.c[mi][ni][hf * 2 + 1] * scale);
            }
        }
    }
}

// Final projection: A half, fp32 row-major out + bias
__global__ __launch_bounds__(256) void gemm_out(
    const __half* __restrict__ A, const __half* __restrict__ W,
    const float* __restrict__ bias, float* __restrict__ out)
{
    GemmCore gc;
    gc.run(A, W, blockIdx.y * 128, blockIdx.x * 64);

    #pragma unroll
    for (int mi = 0; mi < 2; mi++) {
        #pragma unroll
        for (int hf = 0; hf < 2; hf++) {
            const int m = blockIdx.y * 128 + gc.wm0 + mi * 16 + gc.qrow + hf * 8;
            #pragma unroll
            for (int ni = 0; ni < 4; ni++) {
                const int n = blockIdx.x * 64 + gc.wn0 + ni * 8 + gc.qcol * 2;
                float2 bb = *(const float2*)&bias[n];
                *(float2*)&out[(size_t)m * EMB + n] =
                    make_float2(gc.c[mi][ni][hf * 2] + bb.x,
                                gc.c[mi][ni][hf * 2 + 1] + bb.y);
            }
        }
    }
}

// ============================================================================
// Flash attention (R14 passing, unchanged): fp16, ldmatrix + 3-stage cp.async
// K/V ring (distance 2), exp2-domain softmax, 8 warps / 128 q-rows, LPT.
// ============================================================================
#define FP    72
#define FTILE (64 * FP)            // halves per tile
#define FBUFB (2 * FTILE * 2)      // bytes per (Ks,Vs) stage = 18432
#define FSMEM (3 * FBUFB + 2 * FTILE * 2)   // 3 stages + Ps = 73728

__global__ __launch_bounds__(256, 2) void flash_mma(
    const __half* __restrict__ Q, const __half* __restrict__ K,
    const __half* __restrict__ V, __half* __restrict__ O)
{
    extern __shared__ __align__(16) char dynsm[];
    __half* Ks0 = (__half*)dynsm;                  // stage s at + s*FBUFB
    __half* Vs0 = Ks0 + FTILE;
    __half* Ps  = (__half*)(dynsm + 3 * FBUFB);    // Ps[grp] at + grp*FTILE

    const int qt = gridDim.x - 1 - blockIdx.x;     // heavy tiles first (LPT)
    const int bh = blockIdx.y;
    const size_t base = (size_t)bh * SEQ * HDIM;
    const __half* Qb = Q + base;
    const __half* Kb = K + base;
    const __half* Vb = V + base;

    const int tid  = threadIdx.x;
    const int wid  = tid >> 5;
    const int grp  = wid >> 2;
    const int w16  = (wid & 3) * 16;
    const int lid  = tid & 31;
    const int qrow = lid >> 2;
    const int qcol = lid & 3;
    const int q0   = qt * 128;
    const int jtmax = 2 * qt + grp;
    const int last  = 2 * qt + 1;
    const unsigned FULL = 0xffffffffu;

    const int i8 = lid & 7;
    const int g1 = (lid >> 3) & 1;
    const int g2 = (lid >> 4) & 1;
    __half* Pg = Ps + grp * FTILE;
    const uint32_t paddr = cvta_smem(Pg) +
        (uint32_t)(((w16 + g1 * 8 + i8) * FP + g2 * 8) * 2);
    uint32_t kaddr[4], vaddr[4];
    {
        const uint32_t kb_ = cvta_smem(Ks0);
        const uint32_t vb_ = cvta_smem(Vs0);
        #pragma unroll
        for (int ntp = 0; ntp < 4; ntp++) {
            kaddr[ntp] = kb_ + (uint32_t)((((2 * ntp + g2) * 8 + i8) * FP + g1 * 8) * 2);
            vaddr[ntp] = vb_ + (uint32_t)(((g1 * 8 + i8) * FP + (2 * ntp + g2) * 8) * 2);
        }
    }

    const uint32_t ksb = cvta_smem(Ks0);
    const uint32_t vsb = cvta_smem(Vs0);
    auto prefetch = [&](int jt, int s) {
        #pragma unroll
        for (int l = 0; l < 2; l++) {
            int idx = tid + l * 256;
            int r   = idx >> 3;
            int c8  = (idx & 7) * 8;
            size_t g = (size_t)(jt * 64 + r) * HDIM + c8;
            uint32_t off = (uint32_t)(r * FP + c8) * 2 + s * FBUFB;
            cp16(ksb + off, &Kb[g]);
            cp16(vsb + off, &Vb[g]);
        }
    };

    prefetch(0, 0); CP_COMMIT();
    prefetch(1, 1); CP_COMMIT();       // last >= 1 always

    #pragma unroll
    for (int l = 0; l < 4; l++) {
        int idx = tid + l * 256;
        int r   = idx >> 3;
        int c8  = (idx & 7) * 8;
        *(uint4*)&Ps[(r >> 6) * FTILE + (r & 63) * FP + c8] =
            *(const uint4*)&Qb[(size_t)(q0 + r) * HDIM + c8];
    }
    __syncthreads();

    uint32_t aq[4][4];
    #pragma unroll
    for (int ks = 0; ks < 4; ks++)
        ldm_x4(aq[ks][0], aq[ks][1], aq[ks][2], aq[ks][3], paddr + ks * 32);

    float o[8][4];
    #pragma unroll
    for (int nt = 0; nt < 8; nt++)
        #pragma unroll
        for (int f = 0; f < 4; f++) o[nt][f] = 0.f;
    float m_lo = -INFINITY, m_hi = -INFINITY, l_lo = 0.f, l_hi = 0.f;

    for (int jt = 0; jt <= last; jt++) {
        if (jt < last) { CP_WAIT(1); } else { CP_WAIT(0); }
        __syncthreads();
        if (jt + 2 <= last) {
            prefetch(jt + 2, (jt + 2) % 3);
            CP_COMMIT();
        }

        if (jt <= jtmax) {
            const uint32_t boff = (jt % 3) * FBUFB;

            float c[8][4];
            #pragma unroll
            for (int nt = 0; nt < 8; nt++)
                #pragma unroll
                for (int f = 0; f < 4; f++) c[nt][f] = 0.f;

            #pragma unroll
            for (int ks = 0; ks < 4; ks++) {
                #pragma unroll
                for (int ntp = 0; ntp < 4; ntp++) {
                    uint32_t b0, b1, b2, b3;
                    ldm_x4(b0, b1, b2, b3, kaddr[ntp] + boff + ks * 32);
                    mma_fp16(c[2*ntp][0], c[2*ntp][1], c[2*ntp][2], c[2*ntp][3],
                             aq[ks][0], aq[ks][1], aq[ks][2], aq[ks][3], b0, b1);
                    mma_fp16(c[2*ntp+1][0], c[2*ntp+1][1], c[2*ntp+1][2], c[2*ntp+1][3],
                             aq[ks][0], aq[ks][1], aq[ks][2], aq[ks][3], b2, b3);
                }
            }

            if (jt == jtmax) {
                #pragma unroll
                for (int nt = 0; nt < 8; nt++) {
                    #pragma unroll
                    for (int f = 0; f < 4; f++) {
                        int kloc = nt * 8 + 2 * qcol + (f & 1);
                        int qloc = w16 + qrow + ((f >> 1) * 8);
                        if (kloc > qloc) c[nt][f] = -INFINITY;
                    }
                }
            }

            float tl = -INFINITY, th = -INFINITY;
            #pragma unroll
            for (int nt = 0; nt < 8; nt++) {
                tl = fmaxf(tl, fmaxf(c[nt][0], c[nt][1]));
                th = fmaxf(th, fmaxf(c[nt][2], c[nt][3]));
            }
            tl = fmaxf(tl, __shfl_xor_sync(FULL, tl, 1, 4));
            tl = fmaxf(tl, __shfl_xor_sync(FULL, tl, 2, 4));
            th = fmaxf(th, __shfl_xor_sync(FULL, th, 1, 4));
            th = fmaxf(th, __shfl_xor_sync(FULL, th, 2, 4));

            float mn_lo = fmaxf(m_lo, tl);
            float mn_hi = fmaxf(m_hi, th);
            float f_lo = ex2f(m_lo - mn_lo);
            float f_hi = ex2f(m_hi - mn_hi);

            float rs_lo = 0.f, rs_hi = 0.f;
            #pragma unroll
            for (int nt = 0; nt < 8; nt++) {
                uint32_t e01 = h2exp2(pack_h2(c[nt][0] - mn_lo, c[nt][1] - mn_lo));
                uint32_t e23 = h2exp2(pack_h2(c[nt][2] - mn_hi, c[nt][3] - mn_hi));
                int col = nt * 8 + 2 * qcol;
                *(uint32_t*)&Pg[(w16 + qrow) * FP + col]     = e01;
                *(uint32_t*)&Pg[(w16 + qrow + 8) * FP + col] = e23;
                float2 f01 = __half22float2(*(__half2*)&e01);
                float2 f23 = __half22float2(*(__half2*)&e23);
                rs_lo += f01.x + f01.y;
                rs_hi += f23.x + f23.y;
            }
            rs_lo += __shfl_xor_sync(FULL, rs_lo, 1, 4);
            rs_lo += __shfl_xor_sync(FULL, rs_lo, 2, 4);
            rs_hi += __shfl_xor_sync(FULL, rs_hi, 1, 4);
            rs_hi += __shfl_xor_sync(FULL, rs_hi, 2, 4);

            l_lo = l_lo * f_lo + rs_lo;
            l_hi = l_hi * f_hi + rs_hi;
            m_lo = mn_lo;
            m_hi = mn_hi;
            #pragma unroll
            for (int nt = 0; nt < 8; nt++) {
                o[nt][0] *= f_lo; o[nt][1] *= f_lo;
                o[nt][2] *= f_hi; o[nt][3] *= f_hi;
            }
            __syncwarp();

            #pragma unroll
            for (int ks = 0; ks < 4; ks++) {
                uint32_t a0, a1, a2, a3;
                ldm_x4(a0, a1, a2, a3, paddr + ks * 32);
                #pragma unroll
                for (int ntp = 0; ntp < 4; ntp++) {
                    uint32_t v0, v1, v2, v3;
                    ldm_x4_t(v0, v1, v2, v3, vaddr[ntp] + boff + ks * (16 * FP * 2));
                    mma_fp16(o[2*ntp][0], o[2*ntp][1], o[2*ntp][2], o[2*ntp][3],
                             a0, a1, a2, a3, v0, v1);
                    mma_fp16(o[2*ntp+1][0], o[2*ntp+1][1], o[2*ntp+1][2], o[2*ntp+1][3],
                             a0, a1, a2, a3, v2, v3);
                }
            }
        }
        __syncthreads();
    }

    const float inv_lo = 1.f / l_lo;
    const float inv_hi = 1.f / l_hi;
    const int b = bh >> 4;
    const int h = bh & (HEADS - 1);
    const int row_lo = q0 + grp * 64 + w16 + qrow;
    const int row_hi = row_lo + 8;
    #pragma unroll
    for (int nt = 0; nt < 8; nt++) {
        const int e = h * HDIM + nt * 8 + 2 * qcol;
        *(uint32_t*)&O[((size_t)(b * SEQ) + row_lo) * EMB + e] =
            pack_h2(o[nt][0] * inv_lo, o[nt][1] * inv_lo);
        *(uint32_t*)&O[((size_t)(b * SEQ) + row_hi) * EMB + e] =
            pack_h2(o[nt][2] * inv_hi, o[nt][3] * inv_hi);
    }
}

// ---------------- launch -----------------------------------------------------
extern "C" void kernel_launch(void* const* d_in, const int* in_sizes, int n_in,
                              void* d_out, int out_size)
{
    const float* x  = (const float*)d_in[0];
    const float* Wq = (const float*)d_in[1];
    const float* Wk = (const float*)d_in[2];
    const float* Wv = (const float*)d_in[3];
    const float* Wo = (const float*)d_in[4];
    const float* bo = (const float*)d_in[5];
    float* out = (float*)d_out;

    __half *Qp, *Kp, *Vp, *Ap, *xh, *Wh;
    cudaGetSymbolAddress((void**)&Qp, g_Qh);
    cudaGetSymbolAddress((void**)&Kp, g_Kh);
    cudaGetSymbolAddress((void**)&Vp, g_Vh);
    cudaGetSymbolAddress((void**)&Ap, g_AOh);
    cudaGetSymbolAddress((void**)&xh, g_xh);
    cudaGetSymbolAddress((void**)&Wh, g_Wh);

    cvt_all<<<(NX + 4 * NWEL) / (256 * 16), 256>>>(x, Wq, Wk, Wv, Wo, xh, Wh);

    cudaFuncSetAttribute(gemm_qkv, cudaFuncAttributeMaxDynamicSharedMemorySize, GSMEM);
    cudaFuncSetAttribute(gemm_out, cudaFuncAttributeMaxDynamicSharedMemorySize, GSMEM);

    const float qscale = 0.125f * 1.4426950408889634f;   // fold log2e
    dim3 gqkv(EMB / 64, MROWS / 128, 3);                 // (16, 64, 3)
    gemm_qkv<<<gqkv, 256, GSMEM>>>(xh, Wh, Qp, Kp, Vp, qscale);

    cudaFuncSetAttribute(flash_mma, cudaFuncAttributeMaxDynamicSharedMemorySize, FSMEM);
    flash_mma<<<dim3(SEQ / 128, BATCH * HEADS), 256, FSMEM>>>(Qp, Kp, Vp, Ap);

    dim3 gg(EMB / 64, MROWS / 128);   // (16, 64)
    gemm_out<<<gg, 256, GSMEM>>>(Ap, Wh + 3 * (size_t)NWEL, bo, out);
}

// round 16
// speedup vs baseline: 1.0933x; 1.0041x over previous
#include <cuda_runtime.h>
#include <cuda_bf16.h>
#include <cuda_fp16.h>
#include <math.h>
#include <cstdint>

// Problem constants
#define BATCH 2
#define SEQ   4096
#define EMB   1024
#define HEADS 16
#define HDIM  64
#define MROWS (BATCH*SEQ)   // 8192

// ---------------- scratch (static device globals; no runtime allocation) ----
__device__ __half g_Qh[(size_t)BATCH*HEADS*SEQ*HDIM];  // (B,H,T,D), scaled 0.125*log2e
__device__ __half g_Kh[(size_t)BATCH*HEADS*SEQ*HDIM];
__device__ __half g_Vh[(size_t)BATCH*HEADS*SEQ*HDIM];
__device__ __half g_AOh[(size_t)BATCH*SEQ*EMB];        // (B,T,E)
__device__ __half g_xh[(size_t)MROWS*EMB];
__device__ __half g_Wh[4][(size_t)EMB*EMB];            // Wq,Wk,Wv,Wo as half

__device__ __forceinline__ uint32_t pack_h2(float a, float b) {
    __half2 h = __floats2half2_rn(a, b);
    return *(uint32_t*)&h;
}

__device__ __forceinline__ uint32_t h2exp2(uint32_t x) {
    uint32_t r;
    asm("ex2.approx.f16x2 %0, %1;" : "=r"(r) : "r"(x));
    return r;
}

__device__ __forceinline__ float ex2f(float x) {
    float r;
    asm("ex2.approx.f32 %0, %1;" : "=f"(r) : "f"(x));
    return r;
}

__device__ __forceinline__ uint32_t cvta_smem(const void* p) {
    uint32_t a;
    asm("{ .reg .u64 t; cvta.to.shared.u64 t, %1; cvt.u32.u64 %0, t; }"
        : "=r"(a) : "l"(p));
    return a;
}

__device__ __forceinline__ void cp16(uint32_t smem, const void* g) {
    asm volatile("cp.async.cg.shared.global [%0], [%1], 16;" :: "r"(smem), "l"(g));
}
#define CP_COMMIT() asm volatile("cp.async.commit_group;" ::: "memory")
#define CP_WAIT(n)  asm volatile("cp.async.wait_group %0;" :: "n"(n) : "memory")

__device__ __forceinline__ void ldm_x4(
    uint32_t& r0, uint32_t& r1, uint32_t& r2, uint32_t& r3, uint32_t addr)
{
    asm volatile("ldmatrix.sync.aligned.m8n8.x4.shared.b16 {%0,%1,%2,%3}, [%4];"
        : "=r"(r0), "=r"(r1), "=r"(r2), "=r"(r3) : "r"(addr));
}

__device__ __forceinline__ void ldm_x4_t(
    uint32_t& r0, uint32_t& r1, uint32_t& r2, uint32_t& r3, uint32_t addr)
{
    asm volatile("ldmatrix.sync.aligned.m8n8.x4.trans.shared.b16 {%0,%1,%2,%3}, [%4];"
        : "=r"(r0), "=r"(r1), "=r"(r2), "=r"(r3) : "r"(addr));
}

__device__ __forceinline__ void mma_fp16(
    float& c0, float& c1, float& c2, float& c3,
    uint32_t a0, uint32_t a1, uint32_t a2, uint32_t a3,
    uint32_t b0, uint32_t b1)
{
    asm volatile(
        "mma.sync.aligned.m16n8k16.row.col.f32.f16.f16.f32 "
        "{%0,%1,%2,%3}, {%4,%5,%6,%7}, {%8,%9}, {%0,%1,%2,%3};"
        : "+f"(c0), "+f"(c1), "+f"(c2), "+f"(c3)
        : "r"(a0), "r"(a1), "r"(a2), "r"(a3), "r"(b0), "r"(b1));
}

// ---------------- fused fp32 -> fp16 convert (x + 4 weights, 16/thread) -----
#define NX   (MROWS*EMB)     // 8388608
#define NWEL (EMB*EMB)       // 1048576 = 2^20

__global__ __launch_bounds__(256) void cvt_all(
    const float* __restrict__ x,
    const float* __restrict__ wq, const float* __restrict__ wk,
    const float* __restrict__ wv, const float* __restrict__ wo,
    __half* __restrict__ xh, __half* __restrict__ wh)
{
    size_t i = ((size_t)blockIdx.x * 256 + threadIdx.x) * 16;
    const float* src;
    __half* dst;
    size_t off;
    if (i < NX) { src = x; dst = xh; off = i; }
    else {
        size_t j = i - NX;
        int w = (int)(j >> 20);
        src = (w == 0) ? wq : (w == 1) ? wk : (w == 2) ? wv : wo;
        dst = wh + (size_t)w * NWEL;
        off = j & (NWEL - 1);
    }
    #pragma unroll
    for (int l = 0; l < 2; l++) {
        float4 a = *(const float4*)&src[off + l * 8];
        float4 b = *(const float4*)&src[off + l * 8 + 4];
        *(uint4*)&dst[off + l * 8] = make_uint4(
            pack_h2(a.x, a.y), pack_h2(a.z, a.w),
            pack_h2(b.x, b.y), pack_h2(b.z, b.w));
    }
}

// ============================================================================
// fp16 GEMM core: CTA 128x64x32, 256 thr, warp tile 32x32 (8 warps, 4m x 2n).
// 3-stage cp.async ring, prefetch distance 2, ldmatrix fragments.
// __launch_bounds__(256,4) caps regs at 64 -> 4 CTAs/SM.
// ============================================================================
#define GPH    40                      // halves per smem row (80 B)
#define GSTA   (128 * GPH * 2)         // A bytes per stage (10240)
#define GSTB   (64 * GPH * 2)          // B bytes per stage (5120)
#define GSB    (GSTA + GSTB)           // stage bytes = 15360
#define GSMEM  (3 * GSB)               // 46080
#define NCHUNK (EMB / 32)              // 32

struct GemmCore {
    float c[2][4][4];
    int qrow, qcol, wm0, wn0;

    __device__ __forceinline__ void run(
        const __half* __restrict__ A, const __half* __restrict__ W,
        int row0, int col0)
    {
        extern __shared__ __align__(16) char gsm[];
        const uint32_t asb = cvta_smem(gsm);       // A of stage 0
        const uint32_t bsb = asb + GSTA;           // B of stage 0

        const int tid = threadIdx.x;
        const int wid = tid >> 5;
        const int lid = tid & 31;
        qrow = lid >> 2;
        qcol = lid & 3;
        wm0 = (wid & 3) * 32;          // 4 m-positions
        wn0 = (wid >> 2) * 32;         // 2 n-positions

        const int i16 = lid & 15;
        const int g8  = ((lid >> 4) & 1) * 8;
        uint32_t aaddr[2], baddr[2];
        #pragma unroll
        for (int mi = 0; mi < 2; mi++)
            aaddr[mi] = asb + (uint32_t)(((wm0 + mi * 16 + i16) * GPH + g8) * 2);
        #pragma unroll
        for (int nip = 0; nip < 2; nip++)
            baddr[nip] = bsb + (uint32_t)(((wn0 + nip * 16 + i16) * GPH + g8) * 2);

        auto prefetch = [&](int kc, int slot) {
            const int k0 = kc * 32;
            const uint32_t so = slot * GSB;
            #pragma unroll
            for (int l = 0; l < 2; l++) {          // A: 512 cp16
                int idx = tid + l * 256;
                int r   = idx >> 2;                // 0..127
                int c8  = (idx & 3) * 8;
                cp16(asb + so + (uint32_t)(r * GPH + c8) * 2,
                     &A[(size_t)(row0 + r) * EMB + k0 + c8]);
            }
            {                                      // B: 256 cp16
                int r  = tid >> 2;                 // 0..63
                int c8 = (tid & 3) * 8;
                cp16(bsb + so + (uint32_t)(r * GPH + c8) * 2,
                     &W[(size_t)(col0 + r) * EMB + k0 + c8]);
            }
        };

        #pragma unroll
        for (int i = 0; i < 2; i++)
            #pragma unroll
            for (int j = 0; j < 4; j++)
                #pragma unroll
                for (int f = 0; f < 4; f++) c[i][j][f] = 0.f;

        prefetch(0, 0); CP_COMMIT();
        prefetch(1, 1); CP_COMMIT();

        for (int kc = 0; kc < NCHUNK; kc++) {
            if (kc + 1 < NCHUNK) { CP_WAIT(1); } else { CP_WAIT(0); }
            __syncthreads();                       // chunk kc ready, old slot drained
            if (kc + 2 < NCHUNK) {
                prefetch(kc + 2, (kc + 2) % 3);
                CP_COMMIT();
            }
            const uint32_t so = (kc % 3) * GSB;

            #pragma unroll
            for (int ks = 0; ks < 2; ks++) {
                const uint32_t koff = so + ks * 32;
                uint32_t a[2][4], b[4][2];
                #pragma unroll
                for (int mi = 0; mi < 2; mi++)
                    ldm_x4(a[mi][0], a[mi][1], a[mi][2], a[mi][3], aaddr[mi] + koff);
                #pragma unroll
                for (int nip = 0; nip < 2; nip++) {
                    uint32_t r0, r1, r2, r3;
                    ldm_x4(r0, r1, r2, r3, baddr[nip] + koff);
                    b[2*nip][0] = r0;   b[2*nip][1] = r2;
                    b[2*nip+1][0] = r1; b[2*nip+1][1] = r3;
                }
                #pragma unroll
                for (int mi = 0; mi < 2; mi++)
                    #pragma unroll
                    for (int ni = 0; ni < 4; ni++)
                        mma_fp16(c[mi][ni][0], c[mi][ni][1], c[mi][ni][2], c[mi][ni][3],
                                 a[mi][0], a[mi][1], a[mi][2], a[mi][3],
                                 b[ni][0], b[ni][1]);
            }
            __syncthreads();
        }
    }
};

// QKV fused: blockIdx.z selects weight / output / scale; scatter half (B,H,T,D)
__global__ __launch_bounds__(256, 4) void gemm_qkv(
    const __half* __restrict__ A, const __half* __restrict__ Wbase,
    __half* __restrict__ Qo, __half* __restrict__ Ko, __half* __restrict__ Vo,
    float qscale)
{
    const int z = blockIdx.z;
    const __half* W = Wbase + (size_t)z * NWEL;
    __half* out = (z == 0) ? Qo : (z == 1) ? Ko : Vo;
    const float scale = (z == 0) ? qscale : 1.0f;

    GemmCore gc;
    gc.run(A, W, blockIdx.y * 128, blockIdx.x * 64);

    #pragma unroll
    for (int mi = 0; mi < 2; mi++) {
        #pragma unroll
        for (int hf = 0; hf < 2; hf++) {
            const int m = blockIdx.y * 128 + gc.wm0 + mi * 16 + gc.qrow + hf * 8;
            const int bi = m >> 12;
            const int t  = m & (SEQ - 1);
            #pragma unroll
            for (int ni = 0; ni < 4; ni++) {
                const int n = blockIdx.x * 64 + gc.wn0 + ni * 8 + gc.qcol * 2;
                const int h = n >> 6;
                const int d = n & (HDIM - 1);
                *(uint32_t*)&out[(((size_t)bi * HEADS + h) * SEQ + t) * HDIM + d] =
                    pack_h2(gc.c[mi][ni][hf * 2] * scale, gc.c[mi][ni][hf * 2 + 1] * scale);
            }
        }
    }
}

// Final projection: A half, fp32 row-major out + bias
__global__ __launch_bounds__(256, 4) void gemm_out(
    const __half* __restrict__ A, const __half* __restrict__ W,
    const float* __restrict__ bias, float* __restrict__ out)
{
    GemmCore gc;
    gc.run(A, W, blockIdx.y * 128, blockIdx.x * 64);

    #pragma unroll
    for (int mi = 0; mi < 2; mi++) {
        #pragma unroll
        for (int hf = 0; hf < 2; hf++) {
            const int m = blockIdx.y * 128 + gc.wm0 + mi * 16 + gc.qrow + hf * 8;
            #pragma unroll
            for (int ni = 0; ni < 4; ni++) {
                const int n = blockIdx.x * 64 + gc.wn0 + ni * 8 + gc.qcol * 2;
                float2 bb = *(const float2*)&bias[n];
                *(float2*)&out[(size_t)m * EMB + n] =
                    make_float2(gc.c[mi][ni][hf * 2] + bb.x,
                                gc.c[mi][ni][hf * 2 + 1] + bb.y);
            }
        }
    }
}

// ============================================================================
// Flash attention (passing, unchanged): fp16, ldmatrix + 3-stage cp.async
// K/V ring (distance 2), exp2-domain softmax, 8 warps / 128 q-rows, LPT.
// ============================================================================
#define FP    72
#define FTILE (64 * FP)            // halves per tile
#define FBUFB (2 * FTILE * 2)      // bytes per (Ks,Vs) stage = 18432
#define FSMEM (3 * FBUFB + 2 * FTILE * 2)   // 3 stages + Ps = 73728

__global__ __launch_bounds__(256, 2) void flash_mma(
    const __half* __restrict__ Q, const __half* __restrict__ K,
    const __half* __restrict__ V, __half* __restrict__ O)
{
    extern __shared__ __align__(16) char dynsm[];
    __half* Ks0 = (__half*)dynsm;                  // stage s at + s*FBUFB
    __half* Vs0 = Ks0 + FTILE;
    __half* Ps  = (__half*)(dynsm + 3 * FBUFB);    // Ps[grp] at + grp*FTILE

    const int qt = gridDim.x - 1 - blockIdx.x;     // heavy tiles first (LPT)
    const int bh = blockIdx.y;
    const size_t base = (size_t)bh * SEQ * HDIM;
    const __half* Qb = Q + base;
    const __half* Kb = K + base;
    const __half* Vb = V + base;

    const int tid  = threadIdx.x;
    const int wid  = tid >> 5;
    const int grp  = wid >> 2;
    const int w16  = (wid & 3) * 16;
    const int lid  = tid & 31;
    const int qrow = lid >> 2;
    const int qcol = lid & 3;
    const int q0   = qt * 128;
    const int jtmax = 2 * qt + grp;
    const int last  = 2 * qt + 1;
    const unsigned FULL = 0xffffffffu;

    const int i8 = lid & 7;
    const int g1 = (lid >> 3) & 1;
    const int g2 = (lid >> 4) & 1;
    __half* Pg = Ps + grp * FTILE;
    const uint32_t paddr = cvta_smem(Pg) +
        (uint32_t)(((w16 + g1 * 8 + i8) * FP + g2 * 8) * 2);
    uint32_t kaddr[4], vaddr[4];
    {
        const uint32_t kb_ = cvta_smem(Ks0);
        const uint32_t vb_ = cvta_smem(Vs0);
        #pragma unroll
        for (int ntp = 0; ntp < 4; ntp++) {
            kaddr[ntp] = kb_ + (uint32_t)((((2 * ntp + g2) * 8 + i8) * FP + g1 * 8) * 2);
            vaddr[ntp] = vb_ + (uint32_t)(((g1 * 8 + i8) * FP + (2 * ntp + g2) * 8) * 2);
        }
    }

    const uint32_t ksb = cvta_smem(Ks0);
    const uint32_t vsb = cvta_smem(Vs0);
    auto prefetch = [&](int jt, int s) {
        #pragma unroll
        for (int l = 0; l < 2; l++) {
            int idx = tid + l * 256;
            int r   = idx >> 3;
            int c8  = (idx & 7) * 8;
            size_t g = (size_t)(jt * 64 + r) * HDIM + c8;
            uint32_t off = (uint32_t)(r * FP + c8) * 2 + s * FBUFB;
            cp16(ksb + off, &Kb[g]);
            cp16(vsb + off, &Vb[g]);
        }
    };

    prefetch(0, 0); CP_COMMIT();
    prefetch(1, 1); CP_COMMIT();       // last >= 1 always

    #pragma unroll
    for (int l = 0; l < 4; l++) {
        int idx = tid + l * 256;
        int r   = idx >> 3;
        int c8  = (idx & 7) * 8;
        *(uint4*)&Ps[(r >> 6) * FTILE + (r & 63) * FP + c8] =
            *(const uint4*)&Qb[(size_t)(q0 + r) * HDIM + c8];
    }
    __syncthreads();

    uint32_t aq[4][4];
    #pragma unroll
    for (int ks = 0; ks < 4; ks++)
        ldm_x4(aq[ks][0], aq[ks][1], aq[ks][2], aq[ks][3], paddr + ks * 32);

    float o[8][4];
    #pragma unroll
    for (int nt = 0; nt < 8; nt++)
        #pragma unroll
        for (int f = 0; f < 4; f++) o[nt][f] = 0.f;
    float m_lo = -INFINITY, m_hi = -INFINITY, l_lo = 0.f, l_hi = 0.f;

    for (int jt = 0; jt <= last; jt++) {
        if (jt < last) { CP_WAIT(1); } else { CP_WAIT(0); }
        __syncthreads();
        if (jt + 2 <= last) {
            prefetch(jt + 2, (jt + 2) % 3);
            CP_COMMIT();
        }

        if (jt <= jtmax) {
            const uint32_t boff = (jt % 3) * FBUFB;

            float c[8][4];
            #pragma unroll
            for (int nt = 0; nt < 8; nt++)
                #pragma unroll
                for (int f = 0; f < 4; f++) c[nt][f] = 0.f;

            #pragma unroll
            for (int ks = 0; ks < 4; ks++) {
                #pragma unroll
                for (int ntp = 0; ntp < 4; ntp++) {
                    uint32_t b0, b1, b2, b3;
                    ldm_x4(b0, b1, b2, b3, kaddr[ntp] + boff + ks * 32);
                    mma_fp16(c[2*ntp][0], c[2*ntp][1], c[2*ntp][2], c[2*ntp][3],
                             aq[ks][0], aq[ks][1], aq[ks][2], aq[ks][3], b0, b1);
                    mma_fp16(c[2*ntp+1][0], c[2*ntp+1][1], c[2*ntp+1][2], c[2*ntp+1][3],
                             aq[ks][0], aq[ks][1], aq[ks][2], aq[ks][3], b2, b3);
                }
            }

            if (jt == jtmax) {
                #pragma unroll
                for (int nt = 0; nt < 8; nt++) {
                    #pragma unroll
                    for (int f = 0; f < 4; f++) {
                        int kloc = nt * 8 + 2 * qcol + (f & 1);
                        int qloc = w16 + qrow + ((f >> 1) * 8);
                        if (kloc > qloc) c[nt][f] = -INFINITY;
                    }
                }
            }

            float tl = -INFINITY, th = -INFINITY;
            #pragma unroll
            for (int nt = 0; nt < 8; nt++) {
                tl = fmaxf(tl, fmaxf(c[nt][0], c[nt][1]));
                th = fmaxf(th, fmaxf(c[nt][2], c[nt][3]));
            }
            tl = fmaxf(tl, __shfl_xor_sync(FULL, tl, 1, 4));
            tl = fmaxf(tl, __shfl_xor_sync(FULL, tl, 2, 4));
            th = fmaxf(th, __shfl_xor_sync(FULL, th, 1, 4));
            th = fmaxf(th, __shfl_xor_sync(FULL, th, 2, 4));

            float mn_lo = fmaxf(m_lo, tl);
            float mn_hi = fmaxf(m_hi, th);
            float f_lo = ex2f(m_lo - mn_lo);
            float f_hi = ex2f(m_hi - mn_hi);

            float rs_lo = 0.f, rs_hi = 0.f;
            #pragma unroll
            for (int nt = 0; nt < 8; nt++) {
                uint32_t e01 = h2exp2(pack_h2(c[nt][0] - mn_lo, c[nt][1] - mn_lo));
                uint32_t e23 = h2exp2(pack_h2(c[nt][2] - mn_hi, c[nt][3] - mn_hi));
                int col = nt * 8 + 2 * qcol;
                *(uint32_t*)&Pg[(w16 + qrow) * FP + col]     = e01;
                *(uint32_t*)&Pg[(w16 + qrow + 8) * FP + col] = e23;
                float2 f01 = __half22float2(*(__half2*)&e01);
                float2 f23 = __half22float2(*(__half2*)&e23);
                rs_lo += f01.x + f01.y;
                rs_hi += f23.x + f23.y;
            }
            rs_lo += __shfl_xor_sync(FULL, rs_lo, 1, 4);
            rs_lo += __shfl_xor_sync(FULL, rs_lo, 2, 4);
            rs_hi += __shfl_xor_sync(FULL, rs_hi, 1, 4);
            rs_hi += __shfl_xor_sync(FULL, rs_hi, 2, 4);

            l_lo = l_lo * f_lo + rs_lo;
            l_hi = l_hi * f_hi + rs_hi;
            m_lo = mn_lo;
            m_hi = mn_hi;
            #pragma unroll
            for (int nt = 0; nt < 8; nt++) {
                o[nt][0] *= f_lo; o[nt][1] *= f_lo;
                o[nt][2] *= f_hi; o[nt][3] *= f_hi;
            }
            __syncwarp();

            #pragma unroll
            for (int ks = 0; ks < 4; ks++) {
                uint32_t a0, a1, a2, a3;
                ldm_x4(a0, a1, a2, a3, paddr + ks * 32);
                #pragma unroll
                for (int ntp = 0; ntp < 4; ntp++) {
                    uint32_t v0, v1, v2, v3;
                    ldm_x4_t(v0, v1, v2, v3, vaddr[ntp] + boff + ks * (16 * FP * 2));
                    mma_fp16(o[2*ntp][0], o[2*ntp][1], o[2*ntp][2], o[2*ntp][3],
                             a0, a1, a2, a3, v0, v1);
                    mma_fp16(o[2*ntp+1][0], o[2*ntp+1][1], o[2*ntp+1][2], o[2*ntp+1][3],
                             a0, a1, a2, a3, v2, v3);
                }
            }
        }
        __syncthreads();
    }

    const float inv_lo = 1.f / l_lo;
    const float inv_hi = 1.f / l_hi;
    const int b = bh >> 4;
    const int h = bh & (HEADS - 1);
    const int row_lo = q0 + grp * 64 + w16 + qrow;
    const int row_hi = row_lo + 8;
    #pragma unroll
    for (int nt = 0; nt < 8; nt++) {
        const int e = h * HDIM + nt * 8 + 2 * qcol;
        *(uint32_t*)&O[((size_t)(b * SEQ) + row_lo) * EMB + e] =
            pack_h2(o[nt][0] * inv_lo, o[nt][1] * inv_lo);
        *(uint32_t*)&O[((size_t)(b * SEQ) + row_hi) * EMB + e] =
            pack_h2(o[nt][2] * inv_hi, o[nt][3] * inv_hi);
    }
}

// ---------------- launch -----------------------------------------------------
extern "C" void kernel_launch(void* const* d_in, const int* in_sizes, int n_in,
                              void* d_out, int out_size)
{
    const float* x  = (const float*)d_in[0];
    const float* Wq = (const float*)d_in[1];
    const float* Wk = (const float*)d_in[2];
    const float* Wv = (const float*)d_in[3];
    const float* Wo = (const float*)d_in[4];
    const float* bo = (const float*)d_in[5];
    float* out = (float*)d_out;

    __half *Qp, *Kp, *Vp, *Ap, *xh, *Wh;
    cudaGetSymbolAddress((void**)&Qp, g_Qh);
    cudaGetSymbolAddress((void**)&Kp, g_Kh);
    cudaGetSymbolAddress((void**)&Vp, g_Vh);
    cudaGetSymbolAddress((void**)&Ap, g_AOh);
    cudaGetSymbolAddress((void**)&xh, g_xh);
    cudaGetSymbolAddress((void**)&Wh, g_Wh);

    cvt_all<<<(NX + 4 * NWEL) / (256 * 16), 256>>>(x, Wq, Wk, Wv, Wo, xh, Wh);

    cudaFuncSetAttribute(gemm_qkv, cudaFuncAttributeMaxDynamicSharedMemorySize, GSMEM);
    cudaFuncSetAttribute(gemm_out, cudaFuncAttributeMaxDynamicSharedMemorySize, GSMEM);

    const float qscale = 0.125f * 1.4426950408889634f;   // fold log2e
    dim3 gqkv(EMB / 64, MROWS / 128, 3);                 // (16, 64, 3)
    gemm_qkv<<<gqkv, 256, GSMEM>>>(xh, Wh, Qp, Kp, Vp, qscale);

    cudaFuncSetAttribute(flash_mma, cudaFuncAttributeMaxDynamicSharedMemorySize, FSMEM);
    flash_mma<<<dim3(SEQ / 128, BATCH * HEADS), 256, FSMEM>>>(Qp, Kp, Vp, Ap);

    dim3 gg(EMB / 64, MROWS / 128);   // (16, 64)
    gemm_out<<<gg, 256, GSMEM>>>(Ap, Wh + 3 * (size_t)NWEL, bo, out);
}

// round 17
// speedup vs baseline: 1.1230x; 1.0272x over previous
#include <cuda_runtime.h>
#include <cuda_bf16.h>
#include <cuda_fp16.h>
#include <math.h>
#include <cstdint>

// Problem constants
#define BATCH 2
#define SEQ   4096
#define EMB   1024
#define HEADS 16
#define HDIM  64
#define MROWS (BATCH*SEQ)   // 8192

// ---------------- scratch (static device globals; no runtime allocation) ----
__device__ __half g_Qh[(size_t)BATCH*HEADS*SEQ*HDIM];  // (B,H,T,D), scaled 0.125*log2e
__device__ __half g_Kh[(size_t)BATCH*HEADS*SEQ*HDIM];
__device__ __half g_Vh[(size_t)BATCH*HEADS*SEQ*HDIM];
__device__ __half g_AOh[(size_t)BATCH*SEQ*EMB];        // (B,T,E)
__device__ __half g_xh[(size_t)MROWS*EMB];
__device__ __half g_Wh[4][(size_t)EMB*EMB];            // Wq,Wk,Wv,Wo as half

__device__ __forceinline__ uint32_t pack_h2(float a, float b) {
    __half2 h = __floats2half2_rn(a, b);
    return *(uint32_t*)&h;
}

__device__ __forceinline__ uint32_t h2exp2(uint32_t x) {
    uint32_t r;
    asm("ex2.approx.f16x2 %0, %1;" : "=r"(r) : "r"(x));
    return r;
}

__device__ __forceinline__ float ex2f(float x) {
    float r;
    asm("ex2.approx.f32 %0, %1;" : "=f"(r) : "f"(x));
    return r;
}

__device__ __forceinline__ uint32_t cvta_smem(const void* p) {
    uint32_t a;
    asm("{ .reg .u64 t; cvta.to.shared.u64 t, %1; cvt.u32.u64 %0, t; }"
        : "=r"(a) : "l"(p));
    return a;
}

__device__ __forceinline__ void cp16(uint32_t smem, const void* g) {
    asm volatile("cp.async.cg.shared.global [%0], [%1], 16;" :: "r"(smem), "l"(g));
}
#define CP_COMMIT() asm volatile("cp.async.commit_group;" ::: "memory")
#define CP_WAIT(n)  asm volatile("cp.async.wait_group %0;" :: "n"(n) : "memory")

__device__ __forceinline__ void ldm_x4(
    uint32_t& r0, uint32_t& r1, uint32_t& r2, uint32_t& r3, uint32_t addr)
{
    asm volatile("ldmatrix.sync.aligned.m8n8.x4.shared.b16 {%0,%1,%2,%3}, [%4];"
        : "=r"(r0), "=r"(r1), "=r"(r2), "=r"(r3) : "r"(addr));
}

__device__ __forceinline__ void ldm_x4_t(
    uint32_t& r0, uint32_t& r1, uint32_t& r2, uint32_t& r3, uint32_t addr)
{
    asm volatile("ldmatrix.sync.aligned.m8n8.x4.trans.shared.b16 {%0,%1,%2,%3}, [%4];"
        : "=r"(r0), "=r"(r1), "=r"(r2), "=r"(r3) : "r"(addr));
}

__device__ __forceinline__ void mma_fp16(
    float& c0, float& c1, float& c2, float& c3,
    uint32_t a0, uint32_t a1, uint32_t a2, uint32_t a3,
    uint32_t b0, uint32_t b1)
{
    asm volatile(
        "mma.sync.aligned.m16n8k16.row.col.f32.f16.f16.f32 "
        "{%0,%1,%2,%3}, {%4,%5,%6,%7}, {%8,%9}, {%0,%1,%2,%3};"
        : "+f"(c0), "+f"(c1), "+f"(c2), "+f"(c3)
        : "r"(a0), "r"(a1), "r"(a2), "r"(a3), "r"(b0), "r"(b1));
}

// ---------------- fused fp32 -> fp16 convert (x + 4 weights, 16/thread) -----
#define NX   (MROWS*EMB)     // 8388608
#define NWEL (EMB*EMB)       // 1048576 = 2^20

__global__ __launch_bounds__(256) void cvt_all(
    const float* __restrict__ x,
    const float* __restrict__ wq, const float* __restrict__ wk,
    const float* __restrict__ wv, const float* __restrict__ wo,
    __half* __restrict__ xh, __half* __restrict__ wh)
{
    size_t i = ((size_t)blockIdx.x * 256 + threadIdx.x) * 16;
    const float* src;
    __half* dst;
    size_t off;
    if (i < NX) { src = x; dst = xh; off = i; }
    else {
        size_t j = i - NX;
        int w = (int)(j >> 20);
        src = (w == 0) ? wq : (w == 1) ? wk : (w == 2) ? wv : wo;
        dst = wh + (size_t)w * NWEL;
        off = j & (NWEL - 1);
    }
    #pragma unroll
    for (int l = 0; l < 2; l++) {
        float4 a = *(const float4*)&src[off + l * 8];
        float4 b = *(const float4*)&src[off + l * 8 + 4];
        *(uint4*)&dst[off + l * 8] = make_uint4(
            pack_h2(a.x, a.y), pack_h2(a.z, a.w),
            pack_h2(b.x, b.y), pack_h2(b.z, b.w));
    }
}

// ============================================================================
// fp16 GEMM core: CTA 128x64x32, 256 thr, warp tile 32x32 (8 warps, 4m x 2n).
// 3-stage cp.async ring, prefetch distance 2, ldmatrix fragments.
// ONE barrier per chunk (top-of-loop barrier already orders compute(kc-1)
// before prefetch into slot (kc-1)%3).
// ============================================================================
#define GPH    40                      // halves per smem row (80 B)
#define GSTA   (128 * GPH * 2)         // A bytes per stage (10240)
#define GSTB   (64 * GPH * 2)          // B bytes per stage (5120)
#define GSB    (GSTA + GSTB)           // stage bytes = 15360
#define GSMEM  (3 * GSB)               // 46080
#define NCHUNK (EMB / 32)              // 32

struct GemmCore {
    float c[2][4][4];
    int qrow, qcol, wm0, wn0;

    __device__ __forceinline__ void run(
        const __half* __restrict__ A, const __half* __restrict__ W,
        int row0, int col0)
    {
        extern __shared__ __align__(16) char gsm[];
        const uint32_t asb = cvta_smem(gsm);       // A of stage 0
        const uint32_t bsb = asb + GSTA;           // B of stage 0

        const int tid = threadIdx.x;
        const int wid = tid >> 5;
        const int lid = tid & 31;
        qrow = lid >> 2;
        qcol = lid & 3;
        wm0 = (wid & 3) * 32;          // 4 m-positions
        wn0 = (wid >> 2) * 32;         // 2 n-positions

        const int i16 = lid & 15;
        const int g8  = ((lid >> 4) & 1) * 8;
        uint32_t aaddr[2], baddr[2];
        #pragma unroll
        for (int mi = 0; mi < 2; mi++)
            aaddr[mi] = asb + (uint32_t)(((wm0 + mi * 16 + i16) * GPH + g8) * 2);
        #pragma unroll
        for (int nip = 0; nip < 2; nip++)
            baddr[nip] = bsb + (uint32_t)(((wn0 + nip * 16 + i16) * GPH + g8) * 2);

        auto prefetch = [&](int kc, int slot) {
            const int k0 = kc * 32;
            const uint32_t so = slot * GSB;
            #pragma unroll
            for (int l = 0; l < 2; l++) {          // A: 512 cp16
                int idx = tid + l * 256;
                int r   = idx >> 2;                // 0..127
                int c8  = (idx & 3) * 8;
                cp16(asb + so + (uint32_t)(r * GPH + c8) * 2,
                     &A[(size_t)(row0 + r) * EMB + k0 + c8]);
            }
            {                                      // B: 256 cp16
                int r  = tid >> 2;                 // 0..63
                int c8 = (tid & 3) * 8;
                cp16(bsb + so + (uint32_t)(r * GPH + c8) * 2,
                     &W[(size_t)(col0 + r) * EMB + k0 + c8]);
            }
        };

        #pragma unroll
        for (int i = 0; i < 2; i++)
            #pragma unroll
            for (int j = 0; j < 4; j++)
                #pragma unroll
                for (int f = 0; f < 4; f++) c[i][j][f] = 0.f;

        prefetch(0, 0); CP_COMMIT();
        prefetch(1, 1); CP_COMMIT();

        for (int kc = 0; kc < NCHUNK; kc++) {
            if (kc + 1 < NCHUNK) { CP_WAIT(1); } else { CP_WAIT(0); }
            __syncthreads();                       // chunk kc ready; compute(kc-1) done
            if (kc + 2 < NCHUNK) {
                prefetch(kc + 2, (kc + 2) % 3);    // slot (kc-1)%3, safe after barrier
                CP_COMMIT();
            }
            const uint32_t so = (kc % 3) * GSB;

            #pragma unroll
            for (int ks = 0; ks < 2; ks++) {
                const uint32_t koff = so + ks * 32;
                uint32_t a[2][4], b[4][2];
                #pragma unroll
                for (int mi = 0; mi < 2; mi++)
                    ldm_x4(a[mi][0], a[mi][1], a[mi][2], a[mi][3], aaddr[mi] + koff);
                #pragma unroll
                for (int nip = 0; nip < 2; nip++) {
                    uint32_t r0, r1, r2, r3;
                    ldm_x4(r0, r1, r2, r3, baddr[nip] + koff);
                    b[2*nip][0] = r0;   b[2*nip][1] = r2;
                    b[2*nip+1][0] = r1; b[2*nip+1][1] = r3;
                }
                #pragma unroll
                for (int mi = 0; mi < 2; mi++)
                    #pragma unroll
                    for (int ni = 0; ni < 4; ni++)
                        mma_fp16(c[mi][ni][0], c[mi][ni][1], c[mi][ni][2], c[mi][ni][3],
                                 a[mi][0], a[mi][1], a[mi][2], a[mi][3],
                                 b[ni][0], b[ni][1]);
            }
        }
    }
};

// QKV fused: blockIdx.z selects weight / output / scale; scatter half (B,H,T,D)
__global__ __launch_bounds__(256, 4) void gemm_qkv(
    const __half* __restrict__ A, const __half* __restrict__ Wbase,
    __half* __restrict__ Qo, __half* __restrict__ Ko, __half* __restrict__ Vo,
    float qscale)
{
    const int z = blockIdx.z;
    const __half* W = Wbase + (size_t)z * NWEL;
    __half* out = (z == 0) ? Qo : (z == 1) ? Ko : Vo;
    const float scale = (z == 0) ? qscale : 1.0f;

    GemmCore gc;
    gc.run(A, W, blockIdx.y * 128, blockIdx.x * 64);

    #pragma unroll
    for (int mi = 0; mi < 2; mi++) {
        #pragma unroll
        for (int hf = 0; hf < 2; hf++) {
            const int m = blockIdx.y * 128 + gc.wm0 + mi * 16 + gc.qrow + hf * 8;
            const int bi = m >> 12;
            const int t  = m & (SEQ - 1);
            #pragma unroll
            for (int ni = 0; ni < 4; ni++) {
                const int n = blockIdx.x * 64 + gc.wn0 + ni * 8 + gc.qcol * 2;
                const int h = n >> 6;
                const int d = n & (HDIM - 1);
                *(uint32_t*)&out[(((size_t)bi * HEADS + h) * SEQ + t) * HDIM + d] =
                    pack_h2(gc.c[mi][ni][hf * 2] * scale, gc.c[mi][ni][hf * 2 + 1] * scale);
            }
        }
    }
}

// Final projection: A half, fp32 row-major out + bias
__global__ __launch_bounds__(256, 4) void gemm_out(
    const __half* __restrict__ A, const __half* __restrict__ W,
    const float* __restrict__ bias, float* __restrict__ out)
{
    GemmCore gc;
    gc.run(A, W, blockIdx.y * 128, blockIdx.x * 64);

    #pragma unroll
    for (int mi = 0; mi < 2; mi++) {
        #pragma unroll
        for (int hf = 0; hf < 2; hf++) {
            const int m = blockIdx.y * 128 + gc.wm0 + mi * 16 + gc.qrow + hf * 8;
            #pragma unroll
            for (int ni = 0; ni < 4; ni++) {
                const int n = blockIdx.x * 64 + gc.wn0 + ni * 8 + gc.qcol * 2;
                float2 bb = *(const float2*)&bias[n];
                *(float2*)&out[(size_t)m * EMB + n] =
                    make_float2(gc.c[mi][ni][hf * 2] + bb.x,
                                gc.c[mi][ni][hf * 2 + 1] + bb.y);
            }
        }
    }
}

// ============================================================================
// Flash attention: fp16, ldmatrix + 3-stage cp.async K/V ring (distance 2),
// exp2-domain softmax, P KEPT IN REGISTERS (C-frag of S == A-frag of PV after
// half2 packing: a0/a1 from nt=2ks, a2/a3 from nt=2ks+1). No P staging, no
// syncwarp, one barrier per tile. 8 warps / 128 q-rows per CTA, LPT ordering.
// ============================================================================
#define FP    72
#define FTILE (64 * FP)            // halves per tile
#define FBUFB (2 * FTILE * 2)      // bytes per (Ks,Vs) stage = 18432
#define FSMEM (3 * FBUFB + 2 * FTILE * 2)   // 3 stages + Q staging = 73728

__global__ __launch_bounds__(256, 2) void flash_mma(
    const __half* __restrict__ Q, const __half* __restrict__ K,
    const __half* __restrict__ V, __half* __restrict__ O)
{
    extern __shared__ __align__(16) char dynsm[];
    __half* Ks0 = (__half*)dynsm;                  // stage s at + s*FBUFB
    __half* Vs0 = Ks0 + FTILE;
    __half* Ps  = (__half*)(dynsm + 3 * FBUFB);    // Q staging, Ps[grp]

    const int qt = gridDim.x - 1 - blockIdx.x;     // heavy tiles first (LPT)
    const int bh = blockIdx.y;
    const size_t base = (size_t)bh * SEQ * HDIM;
    const __half* Qb = Q + base;
    const __half* Kb = K + base;
    const __half* Vb = V + base;

    const int tid  = threadIdx.x;
    const int wid  = tid >> 5;
    const int grp  = wid >> 2;
    const int w16  = (wid & 3) * 16;
    const int lid  = tid & 31;
    const int qrow = lid >> 2;
    const int qcol = lid & 3;
    const int q0   = qt * 128;
    const int jtmax = 2 * qt + grp;
    const int last  = 2 * qt + 1;
    const unsigned FULL = 0xffffffffu;

    const int i8 = lid & 7;
    const int g1 = (lid >> 3) & 1;
    const int g2 = (lid >> 4) & 1;
    __half* Pg = Ps + grp * FTILE;
    const uint32_t paddr = cvta_smem(Pg) +
        (uint32_t)(((w16 + g1 * 8 + i8) * FP + g2 * 8) * 2);
    uint32_t kaddr[4], vaddr[4];
    {
        const uint32_t kb_ = cvta_smem(Ks0);
        const uint32_t vb_ = cvta_smem(Vs0);
        #pragma unroll
        for (int ntp = 0; ntp < 4; ntp++) {
            kaddr[ntp] = kb_ + (uint32_t)((((2 * ntp + g2) * 8 + i8) * FP + g1 * 8) * 2);
            vaddr[ntp] = vb_ + (uint32_t)(((g1 * 8 + i8) * FP + (2 * ntp + g2) * 8) * 2);
        }
    }

    const uint32_t ksb = cvta_smem(Ks0);
    const uint32_t vsb = cvta_smem(Vs0);
    auto prefetch = [&](int jt, int s) {
        #pragma unroll
        for (int l = 0; l < 2; l++) {
            int idx = tid + l * 256;
            int r   = idx >> 3;
            int c8  = (idx & 7) * 8;
            size_t g = (size_t)(jt * 64 + r) * HDIM + c8;
            uint32_t off = (uint32_t)(r * FP + c8) * 2 + s * FBUFB;
            cp16(ksb + off, &Kb[g]);
            cp16(vsb + off, &Vb[g]);
        }
    };

    prefetch(0, 0); CP_COMMIT();
    prefetch(1, 1); CP_COMMIT();       // last >= 1 always

    #pragma unroll
    for (int l = 0; l < 4; l++) {
        int idx = tid + l * 256;
        int r   = idx >> 3;
        int c8  = (idx & 7) * 8;
        *(uint4*)&Ps[(r >> 6) * FTILE + (r & 63) * FP + c8] =
            *(const uint4*)&Qb[(size_t)(q0 + r) * HDIM + c8];
    }
    __syncthreads();

    uint32_t aq[4][4];
    #pragma unroll
    for (int ks = 0; ks < 4; ks++)
        ldm_x4(aq[ks][0], aq[ks][1], aq[ks][2], aq[ks][3], paddr + ks * 32);

    float o[8][4];
    #pragma unroll
    for (int nt = 0; nt < 8; nt++)
        #pragma unroll
        for (int f = 0; f < 4; f++) o[nt][f] = 0.f;
    float m_lo = -INFINITY, m_hi = -INFINITY, l_lo = 0.f, l_hi = 0.f;

    for (int jt = 0; jt <= last; jt++) {
        // committed groups: 0..min(jt+1,last); guarantee group jt complete
        if (jt < last) { CP_WAIT(1); } else { CP_WAIT(0); }
        __syncthreads();               // also orders compute(jt-1) before refill
        if (jt + 2 <= last) {
            prefetch(jt + 2, (jt + 2) % 3);   // slot (jt-1)%3, safe after barrier
            CP_COMMIT();
        }

        if (jt <= jtmax) {
            const uint32_t boff = (jt % 3) * FBUFB;

            // ---- S = Q K^T (log2 domain) ----
            float c[8][4];
            #pragma unroll
            for (int nt = 0; nt < 8; nt++)
                #pragma unroll
                for (int f = 0; f < 4; f++) c[nt][f] = 0.f;

            #pragma unroll
            for (int ks = 0; ks < 4; ks++) {
                #pragma unroll
                for (int ntp = 0; ntp < 4; ntp++) {
                    uint32_t b0, b1, b2, b3;
                    ldm_x4(b0, b1, b2, b3, kaddr[ntp] + boff + ks * 32);
                    mma_fp16(c[2*ntp][0], c[2*ntp][1], c[2*ntp][2], c[2*ntp][3],
                             aq[ks][0], aq[ks][1], aq[ks][2], aq[ks][3], b0, b1);
                    mma_fp16(c[2*ntp+1][0], c[2*ntp+1][1], c[2*ntp+1][2], c[2*ntp+1][3],
                             aq[ks][0], aq[ks][1], aq[ks][2], aq[ks][3], b2, b3);
                }
            }

            if (jt == jtmax) {
                #pragma unroll
                for (int nt = 0; nt < 8; nt++) {
                    #pragma unroll
                    for (int f = 0; f < 4; f++) {
                        int kloc = nt * 8 + 2 * qcol + (f & 1);
                        int qloc = w16 + qrow + ((f >> 1) * 8);
                        if (kloc > qloc) c[nt][f] = -INFINITY;
                    }
                }
            }

            float tl = -INFINITY, th = -INFINITY;
            #pragma unroll
            for (int nt = 0; nt < 8; nt++) {
                tl = fmaxf(tl, fmaxf(c[nt][0], c[nt][1]));
                th = fmaxf(th, fmaxf(c[nt][2], c[nt][3]));
            }
            tl = fmaxf(tl, __shfl_xor_sync(FULL, tl, 1, 4));
            tl = fmaxf(tl, __shfl_xor_sync(FULL, tl, 2, 4));
            th = fmaxf(th, __shfl_xor_sync(FULL, th, 1, 4));
            th = fmaxf(th, __shfl_xor_sync(FULL, th, 2, 4));

            float mn_lo = fmaxf(m_lo, tl);
            float mn_hi = fmaxf(m_hi, th);
            float f_lo = ex2f(m_lo - mn_lo);
            float f_hi = ex2f(m_hi - mn_hi);

            // ---- P = exp2(S - m), kept in registers as PV A-fragments ----
            uint32_t pe[8][2];
            float rs_lo = 0.f, rs_hi = 0.f;
            #pragma unroll
            for (int nt = 0; nt < 8; nt++) {
                uint32_t e01 = h2exp2(pack_h2(c[nt][0] - mn_lo, c[nt][1] - mn_lo));
                uint32_t e23 = h2exp2(pack_h2(c[nt][2] - mn_hi, c[nt][3] - mn_hi));
                pe[nt][0] = e01;
                pe[nt][1] = e23;
                float2 f01 = __half22float2(*(__half2*)&e01);
                float2 f23 = __half22float2(*(__half2*)&e23);
                rs_lo += f01.x + f01.y;
                rs_hi += f23.x + f23.y;
            }
            rs_lo += __shfl_xor_sync(FULL, rs_lo, 1, 4);
            rs_lo += __shfl_xor_sync(FULL, rs_lo, 2, 4);
            rs_hi += __shfl_xor_sync(FULL, rs_hi, 1, 4);
            rs_hi += __shfl_xor_sync(FULL, rs_hi, 2, 4);

            l_lo = l_lo * f_lo + rs_lo;
            l_hi = l_hi * f_hi + rs_hi;
            m_lo = mn_lo;
            m_hi = mn_hi;
            #pragma unroll
            for (int nt = 0; nt < 8; nt++) {
                o[nt][0] *= f_lo; o[nt][1] *= f_lo;
                o[nt][2] *= f_hi; o[nt][3] *= f_hi;
            }

            // ---- O += P V, A-fragments straight from registers ----
            #pragma unroll
            for (int ks = 0; ks < 4; ks++) {
                uint32_t a0 = pe[2*ks][0];
                uint32_t a1 = pe[2*ks][1];
                uint32_t a2 = pe[2*ks+1][0];
                uint32_t a3 = pe[2*ks+1][1];
                #pragma unroll
                for (int ntp = 0; ntp < 4; ntp++) {
                    uint32_t v0, v1, v2, v3;
                    ldm_x4_t(v0, v1, v2, v3, vaddr[ntp] + boff + ks * (16 * FP * 2));
                    mma_fp16(o[2*ntp][0], o[2*ntp][1], o[2*ntp][2], o[2*ntp][3],
                             a0, a1, a2, a3, v0, v1);
                    mma_fp16(o[2*ntp+1][0], o[2*ntp+1][1], o[2*ntp+1][2], o[2*ntp+1][3],
                             a0, a1, a2, a3, v2, v3);
                }
            }
        }
    }

    const float inv_lo = 1.f / l_lo;
    const float inv_hi = 1.f / l_hi;
    const int b = bh >> 4;
    const int h = bh & (HEADS - 1);
    const int row_lo = q0 + grp * 64 + w16 + qrow;
    const int row_hi = row_lo + 8;
    #pragma unroll
    for (int nt = 0; nt < 8; nt++) {
        const int e = h * HDIM + nt * 8 + 2 * qcol;
        *(uint32_t*)&O[((size_t)(b * SEQ) + row_lo) * EMB + e] =
            pack_h2(o[nt][0] * inv_lo, o[nt][1] * inv_lo);
        *(uint32_t*)&O[((size_t)(b * SEQ) + row_hi) * EMB + e] =
            pack_h2(o[nt][2] * inv_hi, o[nt][3] * inv_hi);
    }
}

// ---------------- launch -----------------------------------------------------
extern "C" void kernel_launch(void* const* d_in, const int* in_sizes, int n_in,
                              void* d_out, int out_size)
{
    const float* x  = (const float*)d_in[0];
    const float* Wq = (const float*)d_in[1];
    const float* Wk = (const float*)d_in[2];
    const float* Wv = (const float*)d_in[3];
    const float* Wo = (const float*)d_in[4];
    const float* bo = (const float*)d_in[5];
    float* out = (float*)d_out;

    __half *Qp, *Kp, *Vp, *Ap, *xh, *Wh;
    cudaGetSymbolAddress((void**)&Qp, g_Qh);
    cudaGetSymbolAddress((void**)&Kp, g_Kh);
    cudaGetSymbolAddress((void**)&Vp, g_Vh);
    cudaGetSymbolAddress((void**)&Ap, g_AOh);
    cudaGetSymbolAddress((void**)&xh, g_xh);
    cudaGetSymbolAddress((void**)&Wh, g_Wh);

    cvt_all<<<(NX + 4 * NWEL) / (256 * 16), 256>>>(x, Wq, Wk, Wv, Wo, xh, Wh);

    cudaFuncSetAttribute(gemm_qkv, cudaFuncAttributeMaxDynamicSharedMemorySize, GSMEM);
    cudaFuncSetAttribute(gemm_out, cudaFuncAttributeMaxDynamicSharedMemorySize, GSMEM);

    const float qscale = 0.125f * 1.4426950408889634f;   // fold log2e
    dim3 gqkv(EMB / 64, MROWS / 128, 3);                 // (16, 64, 3)
    gemm_qkv<<<gqkv, 256, GSMEM>>>(xh, Wh, Qp, Kp, Vp, qscale);

    cudaFuncSetAttribute(flash_mma, cudaFuncAttributeMaxDynamicSharedMemorySize, FSMEM);
    flash_mma<<<dim3(SEQ / 128, BATCH * HEADS), 256, FSMEM>>>(Qp, Kp, Vp, Ap);

    dim3 gg(EMB / 64, MROWS / 128);   // (16, 64)
    gemm_out<<<gg, 256, GSMEM>>>(Ap, Wh + 3 * (size_t)NWEL, bo, out);
}